// round 1
// baseline (speedup 1.0000x reference)
#include <cuda_runtime.h>
#include <cuda_bf16.h>

#define E_EVENTS 1024
#define B_SAMPLES 256
#define DIN 784
#define DH 400
#define DOUT 10

// Scratch (no cudaMalloc allowed): transposed+prepped weights.
__device__ float g_W1T[DIN * DH];   // [784][400] : W1T[p][j] = W1[j][p]
__device__ float g_W2c[DH * DOUT];  // [400][10]  : W2[d][j] + b2[d]/400

__global__ void prep_w1_kernel(const float* __restrict__ W1) {
    int idx = blockIdx.x * blockDim.x + threadIdx.x;
    if (idx < DIN * DH) {
        int p = idx / DH;
        int j = idx - p * DH;
        g_W1T[idx] = W1[j * DIN + p];
    }
}

__global__ void prep_w2_kernel(const float* __restrict__ W2, const float* __restrict__ b2) {
    int idx = blockIdx.x * blockDim.x + threadIdx.x;
    if (idx < DH * DOUT) {
        int j = idx / DOUT;
        int d = idx - j * DOUT;
        // reference: W2.T + b2[None,:]/400  (single add, f32)
        g_W2c[idx] = __fadd_rn(W2[d * DH + j], __fdiv_rn(b2[d], 400.0f));
    }
}

// One CTA per sample. Threads 0..399: layer-1 neurons (h1 in register).
// Warp 13 (threads 416..447), lanes 0..9: layer-2 output dims, pipelined
// one event behind layer 1 via a double-buffered fired bitmask.
__global__ __launch_bounds__(448, 2) void snn_kernel(
    const float* __restrict__ times,
    const int*   __restrict__ pix,
    const float* __restrict__ b1,
    float*       __restrict__ out)
{
    __shared__ float    s_times[E_EVENTS];
    __shared__ int      s_pix[E_EVENTS];
    __shared__ float    s_W2c[DH * DOUT];
    __shared__ unsigned s_mask[2][13];

    const float TAUF = 0.6213349345596119f;  // float(-1/ln(0.2))
    const int b   = blockIdx.x;
    const int tid = threadIdx.x;

    for (int i = tid; i < E_EVENTS; i += 448) {
        s_times[i] = times[b * E_EVENTS + i];
        s_pix[i]   = pix[b * E_EVENTS + i];
    }
    for (int i = tid; i < DH * DOUT; i += 448) s_W2c[i] = g_W2c[i];
    __syncthreads();

    // layer-1 per-thread state
    float h1 = 0.0f, tprev = 0.0f, bias1j = 0.0f;
    if (tid < DH) bias1j = __fdiv_rn(b1[tid], 784.0f);

    // layer-2 per-lane state
    float h2 = 0.0f, cnt = 0.0f, thprev = 0.0f;
    const int l2lane = tid - 416;

    // prefetch event-0 weight row
    float wv = (tid < DH) ? g_W1T[s_pix[0] * DH + tid] : 0.0f;

    for (int e = 0; e < E_EVENTS; ++e) {
        if (tid < 416) {
            // prefetch next event's weight (L2-resident row, coalesced)
            float wnext = 0.0f;
            if (e + 1 < E_EVENTS && tid < DH)
                wnext = g_W1T[s_pix[e + 1] * DH + tid];

            float t     = s_times[e];
            float decay = expf(__fdiv_rn(-(t - tprev), TAUF));
            tprev = t;

            bool fired = false;
            if (tid < DH) {
                // reference order: (h1*decay + W1T[p]) + bias1, no FMA contraction
                h1 = __fadd_rn(__fadd_rn(__fmul_rn(h1, decay), wv), bias1j);
                fired = (h1 >= 0.5f);
                if (fired) h1 = 0.0f;
            }
            unsigned m = __ballot_sync(0xffffffffu, fired);
            if ((tid & 31) == 0) s_mask[e & 1][tid >> 5] = m;
            wv = wnext;
        } else if (e > 0 && l2lane < 10) {
            // process event e-1's fired set (published last iteration)
            const int k = e - 1;
            float t  = s_times[k];
            float th = __fadd_rn(t, 0.1f);
            float d2 = expf(__fdiv_rn(-(th - thprev), TAUF));
            thprev = th;
            h2 = __fmul_rn(h2, d2);
            const int buf = k & 1;
            #pragma unroll
            for (int w = 0; w < 13; ++w) {
                unsigned m = s_mask[buf][w];
                while (m) {
                    int bit = __ffs(m) - 1;
                    m &= m - 1;
                    h2 = __fadd_rn(h2, s_W2c[(w * 32 + bit) * DOUT + l2lane]);
                    if (h2 >= 0.5f) { cnt += 1.0f; h2 = 0.0f; }
                }
            }
        }
        __syncthreads();
    }

    // epilogue: layer 2 for the final event
    if (tid >= 416 && l2lane < 10) {
        const int k = E_EVENTS - 1;
        float t  = s_times[k];
        float th = __fadd_rn(t, 0.1f);
        float d2 = expf(__fdiv_rn(-(th - thprev), TAUF));
        h2 = __fmul_rn(h2, d2);
        const int buf = k & 1;
        #pragma unroll
        for (int w = 0; w < 13; ++w) {
            unsigned m = s_mask[buf][w];
            while (m) {
                int bit = __ffs(m) - 1;
                m &= m - 1;
                h2 = __fadd_rn(h2, s_W2c[(w * 32 + bit) * DOUT + l2lane]);
                if (h2 >= 0.5f) { cnt += 1.0f; h2 = 0.0f; }
            }
        }
        out[b * DOUT + l2lane] = __fdiv_rn(cnt, 64.0f);
    }
}

extern "C" void kernel_launch(void* const* d_in, const int* in_sizes, int n_in,
                              void* d_out, int out_size) {
    const float* times = (const float*)d_in[0];  // [256,1024] f32
    const int*   pixv  = (const int*)d_in[1];    // [256,1024] i32
    const float* W1    = (const float*)d_in[2];  // [400,784]
    const float* b1    = (const float*)d_in[3];  // [400]
    const float* W2    = (const float*)d_in[4];  // [10,400]
    const float* b2    = (const float*)d_in[5];  // [10]
    // d_in[6] = time_window (64), hardcoded below.

    prep_w1_kernel<<<(DIN * DH + 255) / 256, 256>>>(W1);
    prep_w2_kernel<<<(DH * DOUT + 127) / 128, 128>>>(W2, b2);
    snn_kernel<<<B_SAMPLES, 448>>>(times, pixv, b1, (float*)d_out);
}

// round 2
// speedup vs baseline: 1.9281x; 1.9281x over previous
#include <cuda_runtime.h>
#include <cuda_bf16.h>

#define E_EVENTS 1024
#define B_SAMPLES 256
#define DIN 784
#define DH 400
#define DOUT 10
#define CHUNK 32
#define NCHUNK (E_EVENTS / CHUNK)

// Scratch (no cudaMalloc allowed): transposed+prepped weights.
__device__ float g_W1T[DIN * DH];   // [784][400] : W1T[p][j] = W1[j][p]
__device__ float g_W2c[DH * DOUT];  // [400][10]  : W2[d][j] + b2[d]/400

__global__ void prep_w1_kernel(const float* __restrict__ W1) {
    int idx = blockIdx.x * blockDim.x + threadIdx.x;
    if (idx < DIN * DH) {
        int p = idx / DH;
        int j = idx - p * DH;
        g_W1T[idx] = W1[j * DIN + p];
    }
}

__global__ void prep_w2_kernel(const float* __restrict__ W2, const float* __restrict__ b2) {
    int idx = blockIdx.x * blockDim.x + threadIdx.x;
    if (idx < DH * DOUT) {
        int j = idx / DOUT;
        int d = idx - j * DOUT;
        g_W2c[idx] = __fadd_rn(W2[d * DH + j], __fdiv_rn(b2[d], 400.0f));
    }
}

// One CTA per sample. Threads 0..399: layer-1 neurons (h1 in register).
// Warp 13 lanes 0..9: layer-2 output dims, pipelined one CHUNK behind
// layer 1 via double-buffered fired bitmasks.
__global__ __launch_bounds__(448, 2) void snn_kernel(
    const float* __restrict__ times,
    const int*   __restrict__ pix,
    const float* __restrict__ b1,
    float*       __restrict__ out)
{
    __shared__ float    s_times[E_EVENTS];
    __shared__ int      s_pix[E_EVENTS];
    __shared__ float    s_dec1[E_EVENTS];
    __shared__ float    s_dec2[E_EVENTS];
    __shared__ float    s_W2c[DH * DOUT];
    __shared__ unsigned s_mask[2][CHUNK][16];  // padded rows; words 13..15 stay 0

    const float TAUF = 0.6213349345596119f;  // float(-1/ln(0.2))
    const int b    = blockIdx.x;
    const int tid  = threadIdx.x;
    const int warp = tid >> 5;
    const int lane = tid & 31;

    for (int i = tid; i < E_EVENTS; i += 448) {
        s_times[i] = times[b * E_EVENTS + i];
        s_pix[i]   = pix[b * E_EVENTS + i];
    }
    for (int i = tid; i < DH * DOUT; i += 448) s_W2c[i] = g_W2c[i];
    for (int i = tid; i < 2 * CHUNK * 16; i += 448)
        ((unsigned*)s_mask)[i] = 0u;
    __syncthreads();

    // Precompute decays (exact reference f32 expressions)
    for (int e = tid; e < E_EVENTS; e += 448) {
        float t  = s_times[e];
        float tp = (e > 0) ? s_times[e - 1] : 0.0f;
        s_dec1[e] = expf(__fdiv_rn(-(t - tp), TAUF));
        float th  = __fadd_rn(t, 0.1f);
        float thp = (e > 0) ? __fadd_rn(tp, 0.1f) : 0.0f;
        s_dec2[e] = expf(__fdiv_rn(-(th - thp), TAUF));
    }
    __syncthreads();

    // layer-1 per-thread state
    float h1 = 0.0f, bias1j = 0.0f;
    if (tid < DH) bias1j = __fdiv_rn(b1[tid], 784.0f);

    // layer-2 per-lane state
    float h2 = 0.0f, cnt = 0.0f;
    const int l2lane = tid - 416;

    // prefetch event-0 weight row
    float wv = (tid < DH) ? g_W1T[s_pix[0] * DH + tid] : 0.0f;

    for (int k = 0; k < NCHUNK; ++k) {
        if (tid < 416) {
            const int buf = k & 1;
            #pragma unroll 8
            for (int e0 = 0; e0 < CHUNK; ++e0) {
                const int e = k * CHUNK + e0;
                float wnext = 0.0f;
                if (e + 1 < E_EVENTS && tid < DH)
                    wnext = g_W1T[s_pix[e + 1] * DH + tid];
                float d = s_dec1[e];
                bool fired = false;
                if (tid < DH) {
                    // reference order: ((h1*d) + w) + bias, no contraction
                    h1 = __fadd_rn(__fadd_rn(__fmul_rn(h1, d), wv), bias1j);
                    fired = (h1 >= 0.5f);
                    if (fired) h1 = 0.0f;
                }
                unsigned m = __ballot_sync(0xffffffffu, fired);
                if (lane == 0) s_mask[buf][e0][warp] = m;
                wv = wnext;
            }
        } else if (k > 0 && l2lane < 10) {
            const int kb = (k - 1) & 1;
            for (int e0 = 0; e0 < CHUNK; ++e0) {
                const int e = (k - 1) * CHUNK + e0;
                h2 = __fmul_rn(h2, s_dec2[e]);
                const uint4* mp = (const uint4*)&s_mask[kb][e0][0];
                uint4 m0 = mp[0], m1 = mp[1], m2 = mp[2], m3 = mp[3];
                unsigned long long mm[7];
                mm[0] = ((unsigned long long)m0.y << 32) | m0.x;
                mm[1] = ((unsigned long long)m0.w << 32) | m0.z;
                mm[2] = ((unsigned long long)m1.y << 32) | m1.x;
                mm[3] = ((unsigned long long)m1.w << 32) | m1.z;
                mm[4] = ((unsigned long long)m2.y << 32) | m2.x;
                mm[5] = ((unsigned long long)m2.w << 32) | m2.z;
                mm[6] = ((unsigned long long)m3.y << 32) | m3.x;
                #pragma unroll
                for (int c = 0; c < 7; ++c) {
                    unsigned long long m = mm[c];
                    while (m) {
                        int bit = __ffsll(m) - 1;
                        m &= m - 1;
                        int j = c * 64 + bit;
                        h2 = __fadd_rn(h2, s_W2c[j * DOUT + l2lane]);
                        if (h2 >= 0.5f) { cnt += 1.0f; h2 = 0.0f; }
                    }
                }
            }
        }
        __syncthreads();
    }

    // epilogue: layer 2 for the final chunk
    if (tid >= 416 && l2lane < 10) {
        const int kb = (NCHUNK - 1) & 1;
        for (int e0 = 0; e0 < CHUNK; ++e0) {
            const int e = (NCHUNK - 1) * CHUNK + e0;
            h2 = __fmul_rn(h2, s_dec2[e]);
            const uint4* mp = (const uint4*)&s_mask[kb][e0][0];
            uint4 m0 = mp[0], m1 = mp[1], m2 = mp[2], m3 = mp[3];
            unsigned long long mm[7];
            mm[0] = ((unsigned long long)m0.y << 32) | m0.x;
            mm[1] = ((unsigned long long)m0.w << 32) | m0.z;
            mm[2] = ((unsigned long long)m1.y << 32) | m1.x;
            mm[3] = ((unsigned long long)m1.w << 32) | m1.z;
            mm[4] = ((unsigned long long)m2.y << 32) | m2.x;
            mm[5] = ((unsigned long long)m2.w << 32) | m2.z;
            mm[6] = ((unsigned long long)m3.y << 32) | m3.x;
            #pragma unroll
            for (int c = 0; c < 7; ++c) {
                unsigned long long m = mm[c];
                while (m) {
                    int bit = __ffsll(m) - 1;
                    m &= m - 1;
                    int j = c * 64 + bit;
                    h2 = __fadd_rn(h2, s_W2c[j * DOUT + l2lane]);
                    if (h2 >= 0.5f) { cnt += 1.0f; h2 = 0.0f; }
                }
            }
        }
        out[b * DOUT + l2lane] = __fdiv_rn(cnt, 64.0f);
    }
}

extern "C" void kernel_launch(void* const* d_in, const int* in_sizes, int n_in,
                              void* d_out, int out_size) {
    const float* times = (const float*)d_in[0];  // [256,1024] f32
    const int*   pixv  = (const int*)d_in[1];    // [256,1024] i32
    const float* W1    = (const float*)d_in[2];  // [400,784]
    const float* b1    = (const float*)d_in[3];  // [400]
    const float* W2    = (const float*)d_in[4];  // [10,400]
    const float* b2    = (const float*)d_in[5];  // [10]

    prep_w1_kernel<<<(DIN * DH + 255) / 256, 256>>>(W1);
    prep_w2_kernel<<<(DH * DOUT + 127) / 128, 128>>>(W2, b2);
    snn_kernel<<<B_SAMPLES, 448>>>(times, pixv, b1, (float*)d_out);
}